// round 12
// baseline (speedup 1.0000x reference)
#include <cuda_runtime.h>
#include <cstddef>
#include <math.h>

#define T_STEPS 32
#define NB      64
#define LEN0    2048
#define L1      1023
#define L2      511
#define C1      32
#define C2      64

// ---- output layout offsets ----
static const size_t O_SPK0 = 0;
static const size_t O_SPK1 = (size_t)T_STEPS*NB*32736;
static const size_t O_SPK2 = O_SPK1 + (size_t)T_STEPS*NB*32704;
static const size_t O_SPK3 = O_SPK2 + (size_t)T_STEPS*NB*256;
static const size_t O_MEM0 = O_SPK3 + (size_t)T_STEPS*NB*2;
static const size_t O_MEM1 = O_MEM0 + (size_t)T_STEPS*NB*32736;
static const size_t O_MEM2 = O_MEM1 + (size_t)T_STEPS*NB*32704;
static const size_t O_MEM3 = O_MEM2 + (size_t)T_STEPS*NB*256;

// ---- persistent state / scratch ----
__device__ float    g_mem0[NB*C1*L1];
__device__ float    g_mem1[NB*C2*L2];
__device__ float    g_mem2[NB*256];
__device__ float    g_mem3[NB*2];
__device__ unsigned g_mask[2][NB*L1];
__device__ float    g_feat[2*NB*128];
// LUT: [grp(16)][kb(12)][v(256)] float4 (4 oc per group)
__device__ __align__(16) float g_lut[16*12*256*4];

// k_fused dynamic smem: 48KB LUT shared + 2 per-half slices
// slice: masks 4128 + sc 16368 + aux 64 = 20560
#define SM_HALF   20560
#define SM_BASE   49152
#define SMEM2     (SM_BASE + 2*SM_HALF)   // 90,272 B -> 2 CTAs/SM @512thr

// ================= scalar compensated helpers =================
__device__ __forceinline__ void twoSum(float a, float b, float& s, float& e) {
    s = a + b;
    float bp = s - a;
    float ap = s - bp;
    e = (b - bp) + (a - ap);
}
__device__ __forceinline__ void kadd(float& s, float& c, float v) {
    float t, e;
    twoSum(s, v, t, e);
    c += e;
    s = t;
}
__device__ __forceinline__ void kfma(float& s, float& c, float a, float b) {
    float p = a * b;
    float e = fmaf(a, b, -p);
    kadd(s, c, p);
    c += e;
}

// ================= init: zero membrane states =================
__global__ void k_init() {
    const int n0 = NB*C1*L1, n1 = NB*C2*L2, n2 = NB*256, n3 = NB*2;
    const int n = n0 + n1 + n2 + n3;
    for (int i = blockIdx.x*blockDim.x + threadIdx.x; i < n; i += gridDim.x*blockDim.x) {
        if (i < n0) g_mem0[i] = 0.f;
        else if (i < n0+n1) g_mem1[i-n0] = 0.f;
        else if (i < n0+n1+n2) g_mem2[i-n0-n1] = 0.f;
        else g_mem3[i-n0-n1-n2] = 0.f;
    }
}

// ================= LUT build (double, rounded once) =================
__global__ void k_lut(const float* __restrict__ w2) {
    int i = blockIdx.x*blockDim.x + threadIdx.x;
    if (i >= 16*12*256*4) return;
    int ocl = i & 3;
    int v   = (i >> 2) & 255;
    int tt  = i >> 10;
    int kb  = tt % 12;
    int g   = tt / 12;
    int k   = kb >> 2;
    int b4  = kb & 3;
    int oc  = g*4 + ocl;
    double s = 0.0;
    #pragma unroll
    for (int bit = 0; bit < 8; bit++)
        if ((v >> bit) & 1)
            s += (double)w2[(oc*32 + b4*8 + bit)*3 + k];
    g_lut[i] = (float)s;
}

// ================= stage1 task: conv1 + maxpool + LIF0 (one tile, 256 lanes) =
// exact compensated recompute of the pool-winning window;
// two independent 6-term chains (ILP) merged by a final twoSum — the
// compensated result differs from the single-chain order only at ~2^-48.
__device__ __forceinline__ void stage1_task(
        const float* sw, const float* sb, float th,
        int b, int tile, int ts, int ltid,
        const float* __restrict__ x, float* __restrict__ out)
{
    int l1 = tile*256 + ltid;
    if (l1 >= L1) return;

    const float* xb = x + (((size_t)b*T_STEPS + ts)*4)*LEN0;
    float xr[4][5];
    #pragma unroll
    for (int c = 0; c < 4; c++)
        #pragma unroll
        for (int j = 0; j < 5; j++) {
            int gi = 2*l1 - 1 + j;
            xr[c][j] = (gi >= 0 && gi < LEN0) ? xb[c*LEN0 + gi] : 0.f;
        }

    unsigned mask = 0;
    #pragma unroll 2
    for (int oc = 0; oc < C1; oc++) {
        float bb = sb[oc];
        // prefetch membrane state early (hides L2 latency under math below)
        int   sidx = (b*C1 + oc)*L1 + l1;
        float mem  = g_mem0[sidx];

        float y0 = bb, y1 = bb, y2 = bb;
        #pragma unroll
        for (int c = 0; c < 4; c++) {
            float w0 = sw[oc*12 + c*3 + 0];
            float w1v = sw[oc*12 + c*3 + 1];
            float w2v = sw[oc*12 + c*3 + 2];
            y0 = fmaf(w0, xr[c][0], fmaf(w1v, xr[c][1], fmaf(w2v, xr[c][2], y0)));
            y1 = fmaf(w0, xr[c][1], fmaf(w1v, xr[c][2], fmaf(w2v, xr[c][3], y1)));
            y2 = fmaf(w0, xr[c][2], fmaf(w1v, xr[c][3], fmaf(w2v, xr[c][4], y2)));
        }
        int dmax = 0;
        float ymax = y0;
        if (y1 > ymax) { ymax = y1; dmax = 1; }
        if (y2 > ymax) { ymax = y2; dmax = 2; }

        // exact recompute: two parallel compensated chains, merged once
        float sA = bb, cA = 0.f;
        float sB = 0.f, cB = 0.f;
        #pragma unroll
        for (int k = 0; k < 3; k++) {
            kfma(sA, cA, sw[oc*12 + 0*3 + k], xr[0][dmax + k]);
            kfma(sB, cB, sw[oc*12 + 2*3 + k], xr[2][dmax + k]);
        }
        #pragma unroll
        for (int k = 0; k < 3; k++) {
            kfma(sA, cA, sw[oc*12 + 1*3 + k], xr[1][dmax + k]);
            kfma(sB, cB, sw[oc*12 + 3*3 + k], xr[3][dmax + k]);
        }
        float sM, eM;
        twoSum(sA, sB, sM, eM);
        float cur = sM + ((cA + cB) + eM);

        float rst  = (mem - th > 0.f) ? 1.f : 0.f;
        float memn = fmaf(0.5f, mem, cur) - rst*th;
        g_mem0[sidx] = memn;
        float spk = (memn - th > 0.f) ? 1.f : 0.f;
        if (spk > 0.f) mask |= (1u << oc);
        size_t oi = ((size_t)ts*NB + b)*32736 + (size_t)oc*L1 + l1;
        out[O_SPK0 + oi] = spk;
        out[O_MEM0 + oi] = memn;
    }
    g_mask[ts & 1][b*L1 + l1] = mask;
}

// ================= fc body (fc1 + LIF2 + fc2 + LIF3), 256-lane half =========
__device__ __forceinline__ void fc_block(
        char* sm, int ltid, int b, int ts,
        const float* __restrict__ fc1w, const float* __restrict__ fc1b,
        const float* __restrict__ fc2w, const float* __restrict__ fc2b,
        const float* __restrict__ thr, float* __restrict__ out)
{
    float* sfeat = (float*)sm;          // 128
    float* sfc1o = sfeat + 128;         // 256
    float* sspk2 = sfc1o + 256;         // 256

    if (ltid < 128) sfeat[ltid] = g_feat[(size_t)(ts&1)*NB*128 + b*128 + ltid];
    __syncthreads();

    {
        int w = ltid >> 5, lane = ltid & 31;
        for (int oo = 0; oo < 32; oo++) {
            int o = w*32 + oo;
            float s = 0.f, c = 0.f;
            #pragma unroll
            for (int j = 0; j < 4; j++) {
                int f = lane + 32*j;
                kfma(s, c, fc1w[o*128 + f], sfeat[f]);
            }
            #pragma unroll
            for (int sh = 16; sh; sh >>= 1) {
                float s2 = __shfl_down_sync(0xffffffffu, s, sh);
                float c2 = __shfl_down_sync(0xffffffffu, c, sh);
                float ttv, ee;
                twoSum(s, s2, ttv, ee);
                c = (c + c2) + ee;
                s = ttv;
            }
            if (lane == 0) sfc1o[o] = s + c;
        }
    }
    __syncthreads();

    {
        float th = thr[2];
        int o = ltid;
        float cur = sfc1o[o] + fc1b[o];
        float mem  = g_mem2[b*256 + o];
        float rst  = (mem - th > 0.f) ? 1.f : 0.f;
        float memn = fmaf(0.5f, mem, cur) - rst*th;
        g_mem2[b*256 + o] = memn;
        float spk = (memn - th > 0.f) ? 1.f : 0.f;
        sspk2[o] = spk;
        size_t oi = ((size_t)ts*NB + b)*256 + o;
        out[O_SPK2 + oi] = spk;
        out[O_MEM2 + oi] = memn;
    }
    __syncthreads();

    if (ltid < 32) {
        float a0 = 0.f, e0 = 0.f, a1 = 0.f, e1 = 0.f;
        #pragma unroll
        for (int j = 0; j < 8; j++) {
            int o = ltid + 32*j;
            float s = sspk2[o];
            kadd(a0, e0, fc2w[o] * s);
            kadd(a1, e1, fc2w[256 + o] * s);
        }
        #pragma unroll
        for (int sh = 16; sh; sh >>= 1) {
            float s2 = __shfl_down_sync(0xffffffffu, a0, sh);
            float c2 = __shfl_down_sync(0xffffffffu, e0, sh);
            float ttv, ee;
            twoSum(a0, s2, ttv, ee);
            e0 = (e0 + c2) + ee; a0 = ttv;
            s2 = __shfl_down_sync(0xffffffffu, a1, sh);
            c2 = __shfl_down_sync(0xffffffffu, e1, sh);
            twoSum(a1, s2, ttv, ee);
            e1 = (e1 + c2) + ee; a1 = ttv;
        }
        if (ltid == 0) {
            float th = thr[3];
            float cc[2] = {(a0 + e0) + fc2b[0], (a1 + e1) + fc2b[1]};
            #pragma unroll
            for (int r = 0; r < 2; r++) {
                float mem  = g_mem3[b*2 + r];
                float rst  = (mem - th > 0.f) ? 1.f : 0.f;
                float memn = fmaf(0.5f, mem, cc[r]) - rst*th;
                g_mem3[b*2 + r] = memn;
                float spk = (memn - th > 0.f) ? 1.f : 0.f;
                size_t oi = ((size_t)ts*NB + b)*2 + r;
                out[O_SPK3 + oi] = spk;
                out[O_MEM3 + oi] = memn;
            }
        }
    }
}

// ================= stage2 for one batch (LUT resident; 256-lane half) =======
__device__ __forceinline__ void stage2_batch(
        const float4* sT, unsigned* smask, float4* sc, float* saux,
        int ltid, int g, int b, int t,
        const float* __restrict__ b2, const float* __restrict__ thr,
        float* __restrict__ out)
{
    const unsigned* gm = g_mask[t & 1] + b*L1;

    for (int i = ltid; i < 1032; i += 256)
        smask[i] = (i >= 1 && i <= L1) ? gm[i-1] : 0u;
    if (ltid < 8) saux[ltid] = 0.f;
    if (ltid >= 8 && ltid < 12) saux[ltid] = b2[g*4 + (ltid-8)];
    if (ltid == 12) saux[12] = thr[1];

    // prefetch membrane states for pass B (latency hidden by pass A)
    float pm[2][4];
    #pragma unroll
    for (int it = 0; it < 2; it++) {
        int l = ltid + it*256;
        if (l < L2) {
            #pragma unroll
            for (int o = 0; o < 4; o++)
                pm[it][o] = g_mem1[(b*C2 + g*4 + o)*L2 + l];
        }
    }
    __syncthreads();

    // pass A: conv outputs into sc (zero-byte lookups skipped; exact +0)
    {
        int q0 = ltid*4;
        unsigned mm[6];
        #pragma unroll
        for (int j = 0; j < 6; j++) mm[j] = smask[q0 + j];
        #pragma unroll
        for (int i = 0; i < 4; i++) {
            int q = q0 + i;
            if (q < L1) {
                float4 acc = make_float4(0.f, 0.f, 0.f, 0.f);
                #pragma unroll
                for (int k = 0; k < 3; k++) {
                    unsigned m = mm[i + k];
                    unsigned v0 = m & 255u, v1 = (m >> 8) & 255u;
                    unsigned v2 = (m >> 16) & 255u, v3 = m >> 24;
                    const float4* tk = sT + k*4*256;
                    float4 l0 = make_float4(0.f,0.f,0.f,0.f);
                    float4 l1 = l0, l2v = l0, l3 = l0;
                    if (v0) l0  = tk[v0];
                    if (v1) l1  = tk[256 + v1];
                    if (v2) l2v = tk[512 + v2];
                    if (v3) l3  = tk[768 + v3];
                    acc.x += (l0.x + l1.x) + (l2v.x + l3.x);
                    acc.y += (l0.y + l1.y) + (l2v.y + l3.y);
                    acc.z += (l0.z + l1.z) + (l2v.z + l3.z);
                    acc.w += (l0.w + l1.w) + (l2v.w + l3.w);
                }
                sc[q] = acc;
            }
        }
    }
    __syncthreads();

    // pass B: maxpool + LIF1 + writes + spike counts (mem pre-loaded)
    const float th = saux[12];
    const float bs0 = saux[8], bs1 = saux[9], bs2 = saux[10], bs3 = saux[11];
    float cnt0[4] = {0.f,0.f,0.f,0.f}, cnt1[4] = {0.f,0.f,0.f,0.f};

    #pragma unroll
    for (int it = 0; it < 2; it++) {
        int l = ltid + it*256;
        if (l < L2) {
            float4 c0 = sc[2*l], c1 = sc[2*l + 1], c2 = sc[2*l + 2];
            float cur[4];
            cur[0] = fmaxf(c0.x + bs0, fmaxf(c1.x + bs0, c2.x + bs0));
            cur[1] = fmaxf(c0.y + bs1, fmaxf(c1.y + bs1, c2.y + bs1));
            cur[2] = fmaxf(c0.z + bs2, fmaxf(c1.z + bs2, c2.z + bs2));
            cur[3] = fmaxf(c0.w + bs3, fmaxf(c1.w + bs3, c2.w + bs3));
            #pragma unroll
            for (int o = 0; o < 4; o++) {
                int oc = g*4 + o;
                float mem  = pm[it][o];
                float rst  = (mem - th > 0.f) ? 1.f : 0.f;
                float memn = fmaf(0.5f, mem, cur[o]) - rst*th;
                g_mem1[(b*C2 + oc)*L2 + l] = memn;
                float spk = (memn - th > 0.f) ? 1.f : 0.f;
                size_t oi = ((size_t)t*NB + b)*32704 + (size_t)oc*L2 + l;
                out[O_SPK1 + oi] = spk;
                out[O_MEM1 + oi] = memn;
                if (l < 256)  cnt0[o] += spk;
                if (l >= 255) cnt1[o] += spk;
            }
        }
    }

    {
        int lane = ltid & 31;
        #pragma unroll
        for (int o = 0; o < 4; o++) {
            float a = cnt0[o], c = cnt1[o];
            #pragma unroll
            for (int sh = 16; sh; sh >>= 1) {
                a += __shfl_down_sync(0xffffffffu, a, sh);
                c += __shfl_down_sync(0xffffffffu, c, sh);
            }
            if (lane == 0) {
                atomicAdd(&saux[o*2 + 0], a);
                atomicAdd(&saux[o*2 + 1], c);
            }
        }
    }
    __syncthreads();
    if (ltid < 8)
        g_feat[(size_t)(t&1)*NB*128 + b*128 + g*8 + ltid] = saux[ltid] * 0.00390625f;
}

// ================= prologue: stage1 for t = 0 (256 thr) =================
__global__ void __launch_bounds__(256) k_pro(
        const float* __restrict__ x, const float* __restrict__ w1,
        const float* __restrict__ b1, const float* __restrict__ thr,
        float* __restrict__ out)
{
    __shared__ float sw[C1*12];
    __shared__ float sb[C1];
    __shared__ float sthr[1];
    for (int i = threadIdx.x; i < C1*12; i += 256) sw[i] = w1[i];
    if (threadIdx.x < C1) sb[threadIdx.x] = b1[threadIdx.x];
    if (threadIdx.x == 0) sthr[0] = thr[0];
    __syncthreads();
    stage1_task(sw, sb, sthr[0], blockIdx.y, blockIdx.x, 0, threadIdx.x, x, out);
}

// ================= fused (512 thr): heavy blocks FIRST in grid order ========
// blocks [0,128):   stage1(t+1), 2 tile-tasks per block (one per half) [HEAVY]
// blocks [128,160): fc(t-1), 2 batches per block (one per half)
// blocks [160,416): stage2 (16 g x 16 bquads; each half = 2 serial batches)
__global__ void __launch_bounds__(512, 2) k_fused(
        const float* __restrict__ x,
        const float* __restrict__ w1, const float* __restrict__ b1,
        const float* __restrict__ b2,
        const float* __restrict__ fc1w, const float* __restrict__ fc1b,
        const float* __restrict__ fc2w, const float* __restrict__ fc2b,
        const float* __restrict__ thr, float* __restrict__ out, int t)
{
    extern __shared__ char sm[];
    int bid  = blockIdx.x;
    int tid  = threadIdx.x;
    int half = tid >> 8;
    int ltid = tid & 255;

    if (bid < 128) {
        if (t + 1 < T_STEPS) {
            float* sw = (float*)sm;        // 384
            float* sb = sw + C1*12;        // 32
            float* sthr = sb + C1;
            for (int i = tid; i < C1*12; i += 512) sw[i] = w1[i];
            if (tid < C1) sb[tid] = b1[tid];
            if (tid == 448) sthr[0] = thr[0];
            __syncthreads();
            int r = bid*2 + half;          // 0..255
            stage1_task(sw, sb, sthr[0], r >> 2, r & 3, t + 1, ltid, x, out);
        }
    } else if (bid < 160) {
        if (t >= 1) {
            char* hb = sm + half*2560;
            fc_block(hb, ltid, 2*(bid - 128) + half, t - 1,
                     fc1w, fc1b, fc2w, fc2b, thr, out);
        }
    } else {
        int idx = bid - 160;
        int g  = idx & 15;
        int bq = idx >> 4;
        float4*   sT    = (float4*)sm;
        char*     hb    = sm + SM_BASE + half*SM_HALF;
        unsigned* smask = (unsigned*)hb;
        float4*   sc    = (float4*)(hb + 4128);
        float*    saux  = (float*)(hb + 4128 + 16368);

        const float4* lutg = (const float4*)g_lut + (size_t)g*12*256;
        for (int i = tid; i < 12*256; i += 512) sT[i] = lutg[i];

        int b0 = bq*4 + half*2;
        stage2_batch(sT, smask, sc, saux, ltid, g, b0 + 0, t, b2, thr, out);
        __syncthreads();
        stage2_batch(sT, smask, sc, saux, ltid, g, b0 + 1, t, b2, thr, out);
    }
}

// ================= tail: fc for t = 31 (256 thr, one batch/block) ===========
__global__ void __launch_bounds__(256) k_tail(
        const float* __restrict__ fc1w, const float* __restrict__ fc1b,
        const float* __restrict__ fc2w, const float* __restrict__ fc2b,
        const float* __restrict__ thr, float* __restrict__ out)
{
    __shared__ char sm[(128 + 256 + 256) * 4];
    fc_block(sm, threadIdx.x, blockIdx.x, T_STEPS - 1,
             fc1w, fc1b, fc2w, fc2b, thr, out);
}

extern "C" void kernel_launch(void* const* d_in, const int* in_sizes, int n_in,
                              void* d_out, int out_size)
{
    const float* x   = (const float*)d_in[0];
    const float* c1w = (const float*)d_in[1];
    const float* c1b = (const float*)d_in[2];
    const float* c2w = (const float*)d_in[3];
    const float* c2b = (const float*)d_in[4];
    const float* f1w = (const float*)d_in[5];
    const float* f1b = (const float*)d_in[6];
    const float* f2w = (const float*)d_in[7];
    const float* f2b = (const float*)d_in[8];
    const float* thr = (const float*)d_in[9];
    float* out = (float*)d_out;

    cudaFuncSetAttribute(k_fused, cudaFuncAttributeMaxDynamicSharedMemorySize, SMEM2);

    k_init<<<256, 256>>>();
    k_lut<<<768, 256>>>(c2w);
    k_pro<<<dim3(4, NB), 256>>>(x, c1w, c1b, thr, out);
    for (int t = 0; t < T_STEPS; t++) {
        k_fused<<<416, 512, SMEM2>>>(x, c1w, c1b, c2b, f1w, f1b, f2w, f2b,
                                     thr, out, t);
    }
    k_tail<<<NB, 256>>>(f1w, f1b, f2w, f2b, thr, out);
}

// round 13
// speedup vs baseline: 1.0859x; 1.0859x over previous
#include <cuda_runtime.h>
#include <cstddef>
#include <math.h>

#define T_STEPS 32
#define NB      64
#define LEN0    2048
#define L1      1023
#define L2      511
#define C1      32
#define C2      64

// ---- output layout offsets ----
static const size_t O_SPK0 = 0;
static const size_t O_SPK1 = (size_t)T_STEPS*NB*32736;
static const size_t O_SPK2 = O_SPK1 + (size_t)T_STEPS*NB*32704;
static const size_t O_SPK3 = O_SPK2 + (size_t)T_STEPS*NB*256;
static const size_t O_MEM0 = O_SPK3 + (size_t)T_STEPS*NB*2;
static const size_t O_MEM1 = O_MEM0 + (size_t)T_STEPS*NB*32736;
static const size_t O_MEM2 = O_MEM1 + (size_t)T_STEPS*NB*32704;
static const size_t O_MEM3 = O_MEM2 + (size_t)T_STEPS*NB*256;

// ---- persistent state / scratch ----
__device__ float    g_mem0[NB*C1*L1];
__device__ float    g_mem1[NB*C2*L2];
__device__ float    g_mem2[NB*256];
__device__ float    g_mem3[NB*2];
__device__ unsigned g_mask[2][NB*L1];
__device__ float    g_feat[2*NB*128];
// LUT: [grp(16)][kb(12)][v(256)] float4 (4 oc per group)
__device__ __align__(16) float g_lut[16*12*256*4];

// k_fused dynamic smem: 48KB LUT shared + 2 per-half slices
// slice: masks 4128 + sc 16368 + aux 64 = 20560
#define SM_HALF   20560
#define SM_BASE   49152
#define SMEM2     (SM_BASE + 2*SM_HALF)   // 90,272 B -> 2 CTAs/SM @512thr

// ================= scalar compensated helpers =================
__device__ __forceinline__ void twoSum(float a, float b, float& s, float& e) {
    s = a + b;
    float bp = s - a;
    float ap = s - bp;
    e = (b - bp) + (a - ap);
}
__device__ __forceinline__ void kadd(float& s, float& c, float v) {
    float t, e;
    twoSum(s, v, t, e);
    c += e;
    s = t;
}
__device__ __forceinline__ void kfma(float& s, float& c, float a, float b) {
    float p = a * b;
    float e = fmaf(a, b, -p);
    kadd(s, c, p);
    c += e;
}

// ================= init: zero membrane states =================
__global__ void k_init() {
    const int n0 = NB*C1*L1, n1 = NB*C2*L2, n2 = NB*256, n3 = NB*2;
    const int n = n0 + n1 + n2 + n3;
    for (int i = blockIdx.x*blockDim.x + threadIdx.x; i < n; i += gridDim.x*blockDim.x) {
        if (i < n0) g_mem0[i] = 0.f;
        else if (i < n0+n1) g_mem1[i-n0] = 0.f;
        else if (i < n0+n1+n2) g_mem2[i-n0-n1] = 0.f;
        else g_mem3[i-n0-n1-n2] = 0.f;
    }
}

// ================= LUT build (double, rounded once) =================
__global__ void k_lut(const float* __restrict__ w2) {
    int i = blockIdx.x*blockDim.x + threadIdx.x;
    if (i >= 16*12*256*4) return;
    int ocl = i & 3;
    int v   = (i >> 2) & 255;
    int tt  = i >> 10;
    int kb  = tt % 12;
    int g   = tt / 12;
    int k   = kb >> 2;
    int b4  = kb & 3;
    int oc  = g*4 + ocl;
    double s = 0.0;
    #pragma unroll
    for (int bit = 0; bit < 8; bit++)
        if ((v >> bit) & 1)
            s += (double)w2[(oc*32 + b4*8 + bit)*3 + k];
    g_lut[i] = (float)s;
}

// ================= stage1 task: conv1 + maxpool + LIF0 (one tile, 256 lanes) =
// exact compensated recompute of the pool-winning window;
// two independent 6-term chains (ILP) merged by a final twoSum — the
// compensated result differs from the single-chain order only at ~2^-48.
__device__ __forceinline__ void stage1_task(
        const float* sw, const float* sb, float th,
        int b, int tile, int ts, int ltid,
        const float* __restrict__ x, float* __restrict__ out)
{
    int l1 = tile*256 + ltid;
    if (l1 >= L1) return;

    const float* xb = x + (((size_t)b*T_STEPS + ts)*4)*LEN0;
    float xr[4][5];
    #pragma unroll
    for (int c = 0; c < 4; c++)
        #pragma unroll
        for (int j = 0; j < 5; j++) {
            int gi = 2*l1 - 1 + j;
            xr[c][j] = (gi >= 0 && gi < LEN0) ? xb[c*LEN0 + gi] : 0.f;
        }

    unsigned mask = 0;
    #pragma unroll 2
    for (int oc = 0; oc < C1; oc++) {
        float bb = sb[oc];
        // prefetch membrane state early (hides L2 latency under math below)
        int   sidx = (b*C1 + oc)*L1 + l1;
        float mem  = g_mem0[sidx];

        float y0 = bb, y1 = bb, y2 = bb;
        #pragma unroll
        for (int c = 0; c < 4; c++) {
            float w0 = sw[oc*12 + c*3 + 0];
            float w1v = sw[oc*12 + c*3 + 1];
            float w2v = sw[oc*12 + c*3 + 2];
            y0 = fmaf(w0, xr[c][0], fmaf(w1v, xr[c][1], fmaf(w2v, xr[c][2], y0)));
            y1 = fmaf(w0, xr[c][1], fmaf(w1v, xr[c][2], fmaf(w2v, xr[c][3], y1)));
            y2 = fmaf(w0, xr[c][2], fmaf(w1v, xr[c][3], fmaf(w2v, xr[c][4], y2)));
        }
        int dmax = 0;
        float ymax = y0;
        if (y1 > ymax) { ymax = y1; dmax = 1; }
        if (y2 > ymax) { ymax = y2; dmax = 2; }

        // exact recompute: two parallel compensated chains, merged once
        float sA = bb, cA = 0.f;
        float sB = 0.f, cB = 0.f;
        #pragma unroll
        for (int k = 0; k < 3; k++) {
            kfma(sA, cA, sw[oc*12 + 0*3 + k], xr[0][dmax + k]);
            kfma(sB, cB, sw[oc*12 + 2*3 + k], xr[2][dmax + k]);
        }
        #pragma unroll
        for (int k = 0; k < 3; k++) {
            kfma(sA, cA, sw[oc*12 + 1*3 + k], xr[1][dmax + k]);
            kfma(sB, cB, sw[oc*12 + 3*3 + k], xr[3][dmax + k]);
        }
        float sM, eM;
        twoSum(sA, sB, sM, eM);
        float cur = sM + ((cA + cB) + eM);

        float rst  = (mem - th > 0.f) ? 1.f : 0.f;
        float memn = fmaf(0.5f, mem, cur) - rst*th;
        g_mem0[sidx] = memn;
        float spk = (memn - th > 0.f) ? 1.f : 0.f;
        if (spk > 0.f) mask |= (1u << oc);
        size_t oi = ((size_t)ts*NB + b)*32736 + (size_t)oc*L1 + l1;
        out[O_SPK0 + oi] = spk;
        out[O_MEM0 + oi] = memn;
    }
    g_mask[ts & 1][b*L1 + l1] = mask;
}

// ================= fc body (fc1 + LIF2 + fc2 + LIF3), 256-lane half =========
__device__ __forceinline__ void fc_block(
        char* sm, int ltid, int b, int ts,
        const float* __restrict__ fc1w, const float* __restrict__ fc1b,
        const float* __restrict__ fc2w, const float* __restrict__ fc2b,
        const float* __restrict__ thr, float* __restrict__ out)
{
    float* sfeat = (float*)sm;          // 128
    float* sfc1o = sfeat + 128;         // 256
    float* sspk2 = sfc1o + 256;         // 256

    if (ltid < 128) sfeat[ltid] = g_feat[(size_t)(ts&1)*NB*128 + b*128 + ltid];
    __syncthreads();

    {
        int w = ltid >> 5, lane = ltid & 31;
        for (int oo = 0; oo < 32; oo++) {
            int o = w*32 + oo;
            float s = 0.f, c = 0.f;
            #pragma unroll
            for (int j = 0; j < 4; j++) {
                int f = lane + 32*j;
                kfma(s, c, fc1w[o*128 + f], sfeat[f]);
            }
            #pragma unroll
            for (int sh = 16; sh; sh >>= 1) {
                float s2 = __shfl_down_sync(0xffffffffu, s, sh);
                float c2 = __shfl_down_sync(0xffffffffu, c, sh);
                float ttv, ee;
                twoSum(s, s2, ttv, ee);
                c = (c + c2) + ee;
                s = ttv;
            }
            if (lane == 0) sfc1o[o] = s + c;
        }
    }
    __syncthreads();

    {
        float th = thr[2];
        int o = ltid;
        float cur = sfc1o[o] + fc1b[o];
        float mem  = g_mem2[b*256 + o];
        float rst  = (mem - th > 0.f) ? 1.f : 0.f;
        float memn = fmaf(0.5f, mem, cur) - rst*th;
        g_mem2[b*256 + o] = memn;
        float spk = (memn - th > 0.f) ? 1.f : 0.f;
        sspk2[o] = spk;
        size_t oi = ((size_t)ts*NB + b)*256 + o;
        out[O_SPK2 + oi] = spk;
        out[O_MEM2 + oi] = memn;
    }
    __syncthreads();

    if (ltid < 32) {
        float a0 = 0.f, e0 = 0.f, a1 = 0.f, e1 = 0.f;
        #pragma unroll
        for (int j = 0; j < 8; j++) {
            int o = ltid + 32*j;
            float s = sspk2[o];
            kadd(a0, e0, fc2w[o] * s);
            kadd(a1, e1, fc2w[256 + o] * s);
        }
        #pragma unroll
        for (int sh = 16; sh; sh >>= 1) {
            float s2 = __shfl_down_sync(0xffffffffu, a0, sh);
            float c2 = __shfl_down_sync(0xffffffffu, e0, sh);
            float ttv, ee;
            twoSum(a0, s2, ttv, ee);
            e0 = (e0 + c2) + ee; a0 = ttv;
            s2 = __shfl_down_sync(0xffffffffu, a1, sh);
            c2 = __shfl_down_sync(0xffffffffu, e1, sh);
            twoSum(a1, s2, ttv, ee);
            e1 = (e1 + c2) + ee; a1 = ttv;
        }
        if (ltid == 0) {
            float th = thr[3];
            float cc[2] = {(a0 + e0) + fc2b[0], (a1 + e1) + fc2b[1]};
            #pragma unroll
            for (int r = 0; r < 2; r++) {
                float mem  = g_mem3[b*2 + r];
                float rst  = (mem - th > 0.f) ? 1.f : 0.f;
                float memn = fmaf(0.5f, mem, cc[r]) - rst*th;
                g_mem3[b*2 + r] = memn;
                float spk = (memn - th > 0.f) ? 1.f : 0.f;
                size_t oi = ((size_t)ts*NB + b)*2 + r;
                out[O_SPK3 + oi] = spk;
                out[O_MEM3 + oi] = memn;
            }
        }
    }
}

// ================= stage2 for one batch (LUT resident; 256-lane half) =======
__device__ __forceinline__ void stage2_batch(
        const float4* sT, unsigned* smask, float4* sc, float* saux,
        int ltid, int g, int b, int t,
        const float* __restrict__ b2, const float* __restrict__ thr,
        float* __restrict__ out)
{
    const unsigned* gm = g_mask[t & 1] + b*L1;

    for (int i = ltid; i < 1032; i += 256)
        smask[i] = (i >= 1 && i <= L1) ? gm[i-1] : 0u;
    if (ltid < 8) saux[ltid] = 0.f;
    if (ltid >= 8 && ltid < 12) saux[ltid] = b2[g*4 + (ltid-8)];
    if (ltid == 12) saux[12] = thr[1];

    // prefetch membrane states for pass B (latency hidden by pass A)
    float pm[2][4];
    #pragma unroll
    for (int it = 0; it < 2; it++) {
        int l = ltid + it*256;
        if (l < L2) {
            #pragma unroll
            for (int o = 0; o < 4; o++)
                pm[it][o] = g_mem1[(b*C2 + g*4 + o)*L2 + l];
        }
    }
    __syncthreads();

    // pass A: conv outputs into sc (zero-byte lookups skipped; exact +0)
    {
        int q0 = ltid*4;
        unsigned mm[6];
        #pragma unroll
        for (int j = 0; j < 6; j++) mm[j] = smask[q0 + j];
        #pragma unroll
        for (int i = 0; i < 4; i++) {
            int q = q0 + i;
            if (q < L1) {
                float4 acc = make_float4(0.f, 0.f, 0.f, 0.f);
                #pragma unroll
                for (int k = 0; k < 3; k++) {
                    unsigned m = mm[i + k];
                    unsigned v0 = m & 255u, v1 = (m >> 8) & 255u;
                    unsigned v2 = (m >> 16) & 255u, v3 = m >> 24;
                    const float4* tk = sT + k*4*256;
                    float4 l0 = make_float4(0.f,0.f,0.f,0.f);
                    float4 l1 = l0, l2v = l0, l3 = l0;
                    if (v0) l0  = tk[v0];
                    if (v1) l1  = tk[256 + v1];
                    if (v2) l2v = tk[512 + v2];
                    if (v3) l3  = tk[768 + v3];
                    acc.x += (l0.x + l1.x) + (l2v.x + l3.x);
                    acc.y += (l0.y + l1.y) + (l2v.y + l3.y);
                    acc.z += (l0.z + l1.z) + (l2v.z + l3.z);
                    acc.w += (l0.w + l1.w) + (l2v.w + l3.w);
                }
                sc[q] = acc;
            }
        }
    }
    __syncthreads();

    // pass B: maxpool + LIF1 + writes + spike counts (mem pre-loaded)
    const float th = saux[12];
    const float bs0 = saux[8], bs1 = saux[9], bs2 = saux[10], bs3 = saux[11];
    float cnt0[4] = {0.f,0.f,0.f,0.f}, cnt1[4] = {0.f,0.f,0.f,0.f};

    #pragma unroll
    for (int it = 0; it < 2; it++) {
        int l = ltid + it*256;
        if (l < L2) {
            float4 c0 = sc[2*l], c1 = sc[2*l + 1], c2 = sc[2*l + 2];
            float cur[4];
            cur[0] = fmaxf(c0.x + bs0, fmaxf(c1.x + bs0, c2.x + bs0));
            cur[1] = fmaxf(c0.y + bs1, fmaxf(c1.y + bs1, c2.y + bs1));
            cur[2] = fmaxf(c0.z + bs2, fmaxf(c1.z + bs2, c2.z + bs2));
            cur[3] = fmaxf(c0.w + bs3, fmaxf(c1.w + bs3, c2.w + bs3));
            #pragma unroll
            for (int o = 0; o < 4; o++) {
                int oc = g*4 + o;
                float mem  = pm[it][o];
                float rst  = (mem - th > 0.f) ? 1.f : 0.f;
                float memn = fmaf(0.5f, mem, cur[o]) - rst*th;
                g_mem1[(b*C2 + oc)*L2 + l] = memn;
                float spk = (memn - th > 0.f) ? 1.f : 0.f;
                size_t oi = ((size_t)t*NB + b)*32704 + (size_t)oc*L2 + l;
                out[O_SPK1 + oi] = spk;
                out[O_MEM1 + oi] = memn;
                if (l < 256)  cnt0[o] += spk;
                if (l >= 255) cnt1[o] += spk;
            }
        }
    }

    {
        int lane = ltid & 31;
        #pragma unroll
        for (int o = 0; o < 4; o++) {
            float a = cnt0[o], c = cnt1[o];
            #pragma unroll
            for (int sh = 16; sh; sh >>= 1) {
                a += __shfl_down_sync(0xffffffffu, a, sh);
                c += __shfl_down_sync(0xffffffffu, c, sh);
            }
            if (lane == 0) {
                atomicAdd(&saux[o*2 + 0], a);
                atomicAdd(&saux[o*2 + 1], c);
            }
        }
    }
    __syncthreads();
    if (ltid < 8)
        g_feat[(size_t)(t&1)*NB*128 + b*128 + g*8 + ltid] = saux[ltid] * 0.00390625f;
}

// ================= prologue: stage1 for t = 0 (256 thr) =================
__global__ void __launch_bounds__(256) k_pro(
        const float* __restrict__ x, const float* __restrict__ w1,
        const float* __restrict__ b1, const float* __restrict__ thr,
        float* __restrict__ out)
{
    __shared__ float sw[C1*12];
    __shared__ float sb[C1];
    __shared__ float sthr[1];
    for (int i = threadIdx.x; i < C1*12; i += 256) sw[i] = w1[i];
    if (threadIdx.x < C1) sb[threadIdx.x] = b1[threadIdx.x];
    if (threadIdx.x == 0) sthr[0] = thr[0];
    __syncthreads();
    stage1_task(sw, sb, sthr[0], blockIdx.y, blockIdx.x, 0, threadIdx.x, x, out);
}

// ================= fused (512 thr): round-11 grid order ======================
// blocks [0,256): stage2 (16 g x 16 bquads; each half = 2 serial batches)
// blocks [256,384): stage1(t+1), 2 tile-tasks per block (one per half)
// blocks [384,416): fc(t-1), 2 batches per block (one per half)
__global__ void __launch_bounds__(512, 2) k_fused(
        const float* __restrict__ x,
        const float* __restrict__ w1, const float* __restrict__ b1,
        const float* __restrict__ b2,
        const float* __restrict__ fc1w, const float* __restrict__ fc1b,
        const float* __restrict__ fc2w, const float* __restrict__ fc2b,
        const float* __restrict__ thr, float* __restrict__ out, int t)
{
    extern __shared__ char sm[];
    int bid  = blockIdx.x;
    int tid  = threadIdx.x;
    int half = tid >> 8;
    int ltid = tid & 255;

    if (bid < 256) {
        int g  = bid & 15;
        int bq = bid >> 4;
        float4*   sT    = (float4*)sm;
        char*     hb    = sm + SM_BASE + half*SM_HALF;
        unsigned* smask = (unsigned*)hb;
        float4*   sc    = (float4*)(hb + 4128);
        float*    saux  = (float*)(hb + 4128 + 16368);

        const float4* lutg = (const float4*)g_lut + (size_t)g*12*256;
        for (int i = tid; i < 12*256; i += 512) sT[i] = lutg[i];

        int b0 = bq*4 + half*2;
        stage2_batch(sT, smask, sc, saux, ltid, g, b0 + 0, t, b2, thr, out);
        __syncthreads();
        stage2_batch(sT, smask, sc, saux, ltid, g, b0 + 1, t, b2, thr, out);
    } else if (bid < 384) {
        if (t + 1 < T_STEPS) {
            float* sw = (float*)sm;        // 384
            float* sb = sw + C1*12;        // 32
            float* sthr = sb + C1;
            for (int i = tid; i < C1*12; i += 512) sw[i] = w1[i];
            if (tid < C1) sb[tid] = b1[tid];
            if (tid == 448) sthr[0] = thr[0];
            __syncthreads();
            int r = (bid - 256)*2 + half;   // 0..255
            stage1_task(sw, sb, sthr[0], r >> 2, r & 3, t + 1, ltid, x, out);
        }
    } else {
        if (t >= 1) {
            char* hb = sm + half*2560;
            fc_block(hb, ltid, 2*(bid - 384) + half, t - 1,
                     fc1w, fc1b, fc2w, fc2b, thr, out);
        }
    }
}

// ================= tail: fc for t = 31 (256 thr, one batch/block) ===========
__global__ void __launch_bounds__(256) k_tail(
        const float* __restrict__ fc1w, const float* __restrict__ fc1b,
        const float* __restrict__ fc2w, const float* __restrict__ fc2b,
        const float* __restrict__ thr, float* __restrict__ out)
{
    __shared__ char sm[(128 + 256 + 256) * 4];
    fc_block(sm, threadIdx.x, blockIdx.x, T_STEPS - 1,
             fc1w, fc1b, fc2w, fc2b, thr, out);
}

extern "C" void kernel_launch(void* const* d_in, const int* in_sizes, int n_in,
                              void* d_out, int out_size)
{
    const float* x   = (const float*)d_in[0];
    const float* c1w = (const float*)d_in[1];
    const float* c1b = (const float*)d_in[2];
    const float* c2w = (const float*)d_in[3];
    const float* c2b = (const float*)d_in[4];
    const float* f1w = (const float*)d_in[5];
    const float* f1b = (const float*)d_in[6];
    const float* f2w = (const float*)d_in[7];
    const float* f2b = (const float*)d_in[8];
    const float* thr = (const float*)d_in[9];
    float* out = (float*)d_out;

    cudaFuncSetAttribute(k_fused, cudaFuncAttributeMaxDynamicSharedMemorySize, SMEM2);

    k_init<<<256, 256>>>();
    k_lut<<<768, 256>>>(c2w);
    k_pro<<<dim3(4, NB), 256>>>(x, c1w, c1b, thr, out);
    for (int t = 0; t < T_STEPS; t++) {
        k_fused<<<416, 512, SMEM2>>>(x, c1w, c1b, c2b, f1w, f1b, f2w, f2b,
                                     thr, out, t);
    }
    k_tail<<<NB, 256>>>(f1w, f1b, f2w, f2b, thr, out);
}

// round 14
// speedup vs baseline: 1.2488x; 1.1501x over previous
#include <cuda_runtime.h>
#include <cstddef>
#include <math.h>

#define T_STEPS 32
#define NB      64
#define LEN0    2048
#define L1      1023
#define L2      511
#define C1      32
#define C2      64

// ---- output layout offsets ----
static const size_t O_SPK0 = 0;
static const size_t O_SPK1 = (size_t)T_STEPS*NB*32736;
static const size_t O_SPK2 = O_SPK1 + (size_t)T_STEPS*NB*32704;
static const size_t O_SPK3 = O_SPK2 + (size_t)T_STEPS*NB*256;
static const size_t O_MEM0 = O_SPK3 + (size_t)T_STEPS*NB*2;
static const size_t O_MEM1 = O_MEM0 + (size_t)T_STEPS*NB*32736;
static const size_t O_MEM2 = O_MEM1 + (size_t)T_STEPS*NB*32704;
static const size_t O_MEM3 = O_MEM2 + (size_t)T_STEPS*NB*256;

// ---- persistent state / scratch ----
__device__ float    g_mem0[NB*C1*L1];
__device__ float    g_mem1[NB*C2*L2];
__device__ float    g_mem2[NB*256];
__device__ float    g_mem3[NB*2];
__device__ unsigned g_mask[2][NB*L1];
__device__ float    g_feat[2*NB*128];
// LUT: [grp(16)][kb(12)][v(256)] float4 (4 oc per group)
__device__ __align__(16) float g_lut[16*12*256*4];

// k_fused dynamic smem: 48KB LUT shared + 2 per-half slices
// slice: masks 4128 + sc 16368 + aux 64 = 20560
#define SM_HALF   20560
#define SM_BASE   49152
#define SMEM2     (SM_BASE + 2*SM_HALF)   // 90,272 B -> 2 CTAs/SM @512thr

// ================= scalar compensated helpers =================
__device__ __forceinline__ void twoSum(float a, float b, float& s, float& e) {
    s = a + b;
    float bp = s - a;
    float ap = s - bp;
    e = (b - bp) + (a - ap);
}
__device__ __forceinline__ void kadd(float& s, float& c, float v) {
    float t, e;
    twoSum(s, v, t, e);
    c += e;
    s = t;
}
__device__ __forceinline__ void kfma(float& s, float& c, float a, float b) {
    float p = a * b;
    float e = fmaf(a, b, -p);
    kadd(s, c, p);
    c += e;
}

// ================= init: zero membrane states =================
__global__ void k_init() {
    const int n0 = NB*C1*L1, n1 = NB*C2*L2, n2 = NB*256, n3 = NB*2;
    const int n = n0 + n1 + n2 + n3;
    for (int i = blockIdx.x*blockDim.x + threadIdx.x; i < n; i += gridDim.x*blockDim.x) {
        if (i < n0) g_mem0[i] = 0.f;
        else if (i < n0+n1) g_mem1[i-n0] = 0.f;
        else if (i < n0+n1+n2) g_mem2[i-n0-n1] = 0.f;
        else g_mem3[i-n0-n1-n2] = 0.f;
    }
}

// ================= LUT build (double, rounded once) =================
__global__ void k_lut(const float* __restrict__ w2) {
    int i = blockIdx.x*blockDim.x + threadIdx.x;
    if (i >= 16*12*256*4) return;
    int ocl = i & 3;
    int v   = (i >> 2) & 255;
    int tt  = i >> 10;
    int kb  = tt % 12;
    int g   = tt / 12;
    int k   = kb >> 2;
    int b4  = kb & 3;
    int oc  = g*4 + ocl;
    double s = 0.0;
    #pragma unroll
    for (int bit = 0; bit < 8; bit++)
        if ((v >> bit) & 1)
            s += (double)w2[(oc*32 + b4*8 + bit)*3 + k];
    g_lut[i] = (float)s;
}

// ================= stage1 task: conv1 + maxpool + LIF0 (one tile, 256 lanes) =
__device__ __forceinline__ void stage1_task(
        const float* sw, const float* sb, float th,
        int b, int tile, int ts, int ltid,
        const float* __restrict__ x, float* __restrict__ out)
{
    int l1 = tile*256 + ltid;
    if (l1 >= L1) return;

    const float* xb = x + (((size_t)b*T_STEPS + ts)*4)*LEN0;
    float xr[4][5];
    #pragma unroll
    for (int c = 0; c < 4; c++)
        #pragma unroll
        for (int j = 0; j < 5; j++) {
            int gi = 2*l1 - 1 + j;
            xr[c][j] = (gi >= 0 && gi < LEN0) ? xb[c*LEN0 + gi] : 0.f;
        }

    unsigned mask = 0;
    #pragma unroll 2
    for (int oc = 0; oc < C1; oc++) {
        float bb = sb[oc];
        int   sidx = (b*C1 + oc)*L1 + l1;
        float mem  = g_mem0[sidx];

        float y0 = bb, y1 = bb, y2 = bb;
        #pragma unroll
        for (int c = 0; c < 4; c++) {
            float w0 = sw[oc*12 + c*3 + 0];
            float w1v = sw[oc*12 + c*3 + 1];
            float w2v = sw[oc*12 + c*3 + 2];
            y0 = fmaf(w0, xr[c][0], fmaf(w1v, xr[c][1], fmaf(w2v, xr[c][2], y0)));
            y1 = fmaf(w0, xr[c][1], fmaf(w1v, xr[c][2], fmaf(w2v, xr[c][3], y1)));
            y2 = fmaf(w0, xr[c][2], fmaf(w1v, xr[c][3], fmaf(w2v, xr[c][4], y2)));
        }
        int dmax = 0;
        float ymax = y0;
        if (y1 > ymax) { ymax = y1; dmax = 1; }
        if (y2 > ymax) { ymax = y2; dmax = 2; }

        // exact recompute: two parallel compensated chains, merged once
        float sA = bb, cA = 0.f;
        float sB = 0.f, cB = 0.f;
        #pragma unroll
        for (int k = 0; k < 3; k++) {
            kfma(sA, cA, sw[oc*12 + 0*3 + k], xr[0][dmax + k]);
            kfma(sB, cB, sw[oc*12 + 2*3 + k], xr[2][dmax + k]);
        }
        #pragma unroll
        for (int k = 0; k < 3; k++) {
            kfma(sA, cA, sw[oc*12 + 1*3 + k], xr[1][dmax + k]);
            kfma(sB, cB, sw[oc*12 + 3*3 + k], xr[3][dmax + k]);
        }
        float sM, eM;
        twoSum(sA, sB, sM, eM);
        float cur = sM + ((cA + cB) + eM);

        float rst  = (mem - th > 0.f) ? 1.f : 0.f;
        float memn = fmaf(0.5f, mem, cur) - rst*th;
        g_mem0[sidx] = memn;
        float spk = (memn - th > 0.f) ? 1.f : 0.f;
        if (spk > 0.f) mask |= (1u << oc);
        size_t oi = ((size_t)ts*NB + b)*32736 + (size_t)oc*L1 + l1;
        out[O_SPK0 + oi] = spk;
        out[O_MEM0 + oi] = memn;
    }
    g_mask[ts & 1][b*L1 + l1] = mask;
}

// ================= fc body (fc1 + LIF2 + fc2 + LIF3), 256-lane half =========
__device__ __forceinline__ void fc_block(
        char* sm, int ltid, int b, int ts,
        const float* __restrict__ fc1w, const float* __restrict__ fc1b,
        const float* __restrict__ fc2w, const float* __restrict__ fc2b,
        const float* __restrict__ thr, float* __restrict__ out)
{
    float* sfeat = (float*)sm;          // 128
    float* sfc1o = sfeat + 128;         // 256
    float* sspk2 = sfc1o + 256;         // 256

    if (ltid < 128) sfeat[ltid] = g_feat[(size_t)(ts&1)*NB*128 + b*128 + ltid];
    __syncthreads();

    {
        int w = ltid >> 5, lane = ltid & 31;
        for (int oo = 0; oo < 32; oo++) {
            int o = w*32 + oo;
            float s = 0.f, c = 0.f;
            #pragma unroll
            for (int j = 0; j < 4; j++) {
                int f = lane + 32*j;
                kfma(s, c, fc1w[o*128 + f], sfeat[f]);
            }
            #pragma unroll
            for (int sh = 16; sh; sh >>= 1) {
                float s2 = __shfl_down_sync(0xffffffffu, s, sh);
                float c2 = __shfl_down_sync(0xffffffffu, c, sh);
                float ttv, ee;
                twoSum(s, s2, ttv, ee);
                c = (c + c2) + ee;
                s = ttv;
            }
            if (lane == 0) sfc1o[o] = s + c;
        }
    }
    __syncthreads();

    {
        float th = thr[2];
        int o = ltid;
        float cur = sfc1o[o] + fc1b[o];
        float mem  = g_mem2[b*256 + o];
        float rst  = (mem - th > 0.f) ? 1.f : 0.f;
        float memn = fmaf(0.5f, mem, cur) - rst*th;
        g_mem2[b*256 + o] = memn;
        float spk = (memn - th > 0.f) ? 1.f : 0.f;
        sspk2[o] = spk;
        size_t oi = ((size_t)ts*NB + b)*256 + o;
        out[O_SPK2 + oi] = spk;
        out[O_MEM2 + oi] = memn;
    }
    __syncthreads();

    if (ltid < 32) {
        float a0 = 0.f, e0 = 0.f, a1 = 0.f, e1 = 0.f;
        #pragma unroll
        for (int j = 0; j < 8; j++) {
            int o = ltid + 32*j;
            float s = sspk2[o];
            kadd(a0, e0, fc2w[o] * s);
            kadd(a1, e1, fc2w[256 + o] * s);
        }
        #pragma unroll
        for (int sh = 16; sh; sh >>= 1) {
            float s2 = __shfl_down_sync(0xffffffffu, a0, sh);
            float c2 = __shfl_down_sync(0xffffffffu, e0, sh);
            float ttv, ee;
            twoSum(a0, s2, ttv, ee);
            e0 = (e0 + c2) + ee; a0 = ttv;
            s2 = __shfl_down_sync(0xffffffffu, a1, sh);
            c2 = __shfl_down_sync(0xffffffffu, e1, sh);
            twoSum(a1, s2, ttv, ee);
            e1 = (e1 + c2) + ee; a1 = ttv;
        }
        if (ltid == 0) {
            float th = thr[3];
            float cc[2] = {(a0 + e0) + fc2b[0], (a1 + e1) + fc2b[1]};
            #pragma unroll
            for (int r = 0; r < 2; r++) {
                float mem  = g_mem3[b*2 + r];
                float rst  = (mem - th > 0.f) ? 1.f : 0.f;
                float memn = fmaf(0.5f, mem, cc[r]) - rst*th;
                g_mem3[b*2 + r] = memn;
                float spk = (memn - th > 0.f) ? 1.f : 0.f;
                size_t oi = ((size_t)ts*NB + b)*2 + r;
                out[O_SPK3 + oi] = spk;
                out[O_MEM3 + oi] = memn;
            }
        }
    }
}

// ================= stage2 for one batch (LUT resident; 256-lane half) =======
__device__ __forceinline__ void stage2_batch(
        const float4* sT, unsigned* smask, float4* sc, float* saux,
        int ltid, int g, int b, int t,
        const float* __restrict__ b2, const float* __restrict__ thr,
        float* __restrict__ out)
{
    const unsigned* gm = g_mask[t & 1] + b*L1;

    for (int i = ltid; i < 1032; i += 256)
        smask[i] = (i >= 1 && i <= L1) ? gm[i-1] : 0u;
    if (ltid < 8) saux[ltid] = 0.f;
    if (ltid >= 8 && ltid < 12) saux[ltid] = b2[g*4 + (ltid-8)];
    if (ltid == 12) saux[12] = thr[1];

    // prefetch membrane states for pass B (latency hidden by pass A)
    float pm[2][4];
    #pragma unroll
    for (int it = 0; it < 2; it++) {
        int l = ltid + it*256;
        if (l < L2) {
            #pragma unroll
            for (int o = 0; o < 4; o++)
                pm[it][o] = g_mem1[(b*C2 + g*4 + o)*L2 + l];
        }
    }
    __syncthreads();

    // pass A: conv outputs into sc (zero-byte lookups skipped; exact +0)
    {
        int q0 = ltid*4;
        unsigned mm[6];
        #pragma unroll
        for (int j = 0; j < 6; j++) mm[j] = smask[q0 + j];
        #pragma unroll
        for (int i = 0; i < 4; i++) {
            int q = q0 + i;
            if (q < L1) {
                float4 acc = make_float4(0.f, 0.f, 0.f, 0.f);
                #pragma unroll
                for (int k = 0; k < 3; k++) {
                    unsigned m = mm[i + k];
                    unsigned v0 = m & 255u, v1 = (m >> 8) & 255u;
                    unsigned v2 = (m >> 16) & 255u, v3 = m >> 24;
                    const float4* tk = sT + k*4*256;
                    float4 l0 = make_float4(0.f,0.f,0.f,0.f);
                    float4 l1 = l0, l2v = l0, l3 = l0;
                    if (v0) l0  = tk[v0];
                    if (v1) l1  = tk[256 + v1];
                    if (v2) l2v = tk[512 + v2];
                    if (v3) l3  = tk[768 + v3];
                    acc.x += (l0.x + l1.x) + (l2v.x + l3.x);
                    acc.y += (l0.y + l1.y) + (l2v.y + l3.y);
                    acc.z += (l0.z + l1.z) + (l2v.z + l3.z);
                    acc.w += (l0.w + l1.w) + (l2v.w + l3.w);
                }
                sc[q] = acc;
            }
        }
    }
    __syncthreads();

    // pass B: maxpool + LIF1 + writes + spike counts (mem pre-loaded)
    const float th = saux[12];
    const float bs0 = saux[8], bs1 = saux[9], bs2 = saux[10], bs3 = saux[11];
    float cnt0[4] = {0.f,0.f,0.f,0.f}, cnt1[4] = {0.f,0.f,0.f,0.f};

    #pragma unroll
    for (int it = 0; it < 2; it++) {
        int l = ltid + it*256;
        if (l < L2) {
            float4 c0 = sc[2*l], c1 = sc[2*l + 1], c2 = sc[2*l + 2];
            float cur[4];
            cur[0] = fmaxf(c0.x + bs0, fmaxf(c1.x + bs0, c2.x + bs0));
            cur[1] = fmaxf(c0.y + bs1, fmaxf(c1.y + bs1, c2.y + bs1));
            cur[2] = fmaxf(c0.z + bs2, fmaxf(c1.z + bs2, c2.z + bs2));
            cur[3] = fmaxf(c0.w + bs3, fmaxf(c1.w + bs3, c2.w + bs3));
            #pragma unroll
            for (int o = 0; o < 4; o++) {
                int oc = g*4 + o;
                float mem  = pm[it][o];
                float rst  = (mem - th > 0.f) ? 1.f : 0.f;
                float memn = fmaf(0.5f, mem, cur[o]) - rst*th;
                g_mem1[(b*C2 + oc)*L2 + l] = memn;
                float spk = (memn - th > 0.f) ? 1.f : 0.f;
                size_t oi = ((size_t)t*NB + b)*32704 + (size_t)oc*L2 + l;
                out[O_SPK1 + oi] = spk;
                out[O_MEM1 + oi] = memn;
                if (l < 256)  cnt0[o] += spk;
                if (l >= 255) cnt1[o] += spk;
            }
        }
    }

    {
        int lane = ltid & 31;
        #pragma unroll
        for (int o = 0; o < 4; o++) {
            float a = cnt0[o], c = cnt1[o];
            #pragma unroll
            for (int sh = 16; sh; sh >>= 1) {
                a += __shfl_down_sync(0xffffffffu, a, sh);
                c += __shfl_down_sync(0xffffffffu, c, sh);
            }
            if (lane == 0) {
                atomicAdd(&saux[o*2 + 0], a);
                atomicAdd(&saux[o*2 + 1], c);
            }
        }
    }
    __syncthreads();
    if (ltid < 8)
        g_feat[(size_t)(t&1)*NB*128 + b*128 + g*8 + ltid] = saux[ltid] * 0.00390625f;
}

// ================= prologue: stage1 for t = 0 (256 thr) =================
__global__ void __launch_bounds__(256) k_pro(
        const float* __restrict__ x, const float* __restrict__ w1,
        const float* __restrict__ b1, const float* __restrict__ thr,
        float* __restrict__ out)
{
    __shared__ float sw[C1*12];
    __shared__ float sb[C1];
    __shared__ float sthr[1];
    for (int i = threadIdx.x; i < C1*12; i += 256) sw[i] = w1[i];
    if (threadIdx.x < C1) sb[threadIdx.x] = b1[threadIdx.x];
    if (threadIdx.x == 0) sthr[0] = thr[0];
    __syncthreads();
    stage1_task(sw, sb, sthr[0], blockIdx.y, blockIdx.x, 0, threadIdx.x, x, out);
}

// ================= fused (512 thr): single-wave grid (288 blocks) ===========
// blocks [0,128):   stage2 (16 g x 8 bocts; each half = 4 serial batches)
// blocks [128,256): stage1(t+1), 2 tile-tasks per block (one per half)
// blocks [256,288): fc(t-1), 2 batches per block (one per half)
__global__ void __launch_bounds__(512, 2) k_fused(
        const float* __restrict__ x,
        const float* __restrict__ w1, const float* __restrict__ b1,
        const float* __restrict__ b2,
        const float* __restrict__ fc1w, const float* __restrict__ fc1b,
        const float* __restrict__ fc2w, const float* __restrict__ fc2b,
        const float* __restrict__ thr, float* __restrict__ out, int t)
{
    extern __shared__ char sm[];
    int bid  = blockIdx.x;
    int tid  = threadIdx.x;
    int half = tid >> 8;
    int ltid = tid & 255;

    if (bid < 128) {
        int g    = bid & 15;
        int boct = bid >> 4;               // 0..7 (8 batches each)
        float4*   sT    = (float4*)sm;
        char*     hb    = sm + SM_BASE + half*SM_HALF;
        unsigned* smask = (unsigned*)hb;
        float4*   sc    = (float4*)(hb + 4128);
        float*    saux  = (float*)(hb + 4128 + 16368);

        const float4* lutg = (const float4*)g_lut + (size_t)g*12*256;
        for (int i = tid; i < 12*256; i += 512) sT[i] = lutg[i];

        int b0 = boct*8 + half*4;
        #pragma unroll 1
        for (int it = 0; it < 4; it++) {
            stage2_batch(sT, smask, sc, saux, ltid, g, b0 + it, t, b2, thr, out);
            __syncthreads();
        }
    } else if (bid < 256) {
        if (t + 1 < T_STEPS) {
            float* sw = (float*)sm;        // 384
            float* sb = sw + C1*12;        // 32
            float* sthr = sb + C1;
            for (int i = tid; i < C1*12; i += 512) sw[i] = w1[i];
            if (tid < C1) sb[tid] = b1[tid];
            if (tid == 448) sthr[0] = thr[0];
            __syncthreads();
            int r = (bid - 128)*2 + half;   // 0..255
            stage1_task(sw, sb, sthr[0], r >> 2, r & 3, t + 1, ltid, x, out);
        }
    } else {
        if (t >= 1) {
            char* hb = sm + half*2560;
            fc_block(hb, ltid, 2*(bid - 256) + half, t - 1,
                     fc1w, fc1b, fc2w, fc2b, thr, out);
        }
    }
}

// ================= tail: fc for t = 31 (256 thr, one batch/block) ===========
__global__ void __launch_bounds__(256) k_tail(
        const float* __restrict__ fc1w, const float* __restrict__ fc1b,
        const float* __restrict__ fc2w, const float* __restrict__ fc2b,
        const float* __restrict__ thr, float* __restrict__ out)
{
    __shared__ char sm[(128 + 256 + 256) * 4];
    fc_block(sm, threadIdx.x, blockIdx.x, T_STEPS - 1,
             fc1w, fc1b, fc2w, fc2b, thr, out);
}

extern "C" void kernel_launch(void* const* d_in, const int* in_sizes, int n_in,
                              void* d_out, int out_size)
{
    const float* x   = (const float*)d_in[0];
    const float* c1w = (const float*)d_in[1];
    const float* c1b = (const float*)d_in[2];
    const float* c2w = (const float*)d_in[3];
    const float* c2b = (const float*)d_in[4];
    const float* f1w = (const float*)d_in[5];
    const float* f1b = (const float*)d_in[6];
    const float* f2w = (const float*)d_in[7];
    const float* f2b = (const float*)d_in[8];
    const float* thr = (const float*)d_in[9];
    float* out = (float*)d_out;

    cudaFuncSetAttribute(k_fused, cudaFuncAttributeMaxDynamicSharedMemorySize, SMEM2);

    k_init<<<256, 256>>>();
    k_lut<<<768, 256>>>(c2w);
    k_pro<<<dim3(4, NB), 256>>>(x, c1w, c1b, thr, out);
    for (int t = 0; t < T_STEPS; t++) {
        k_fused<<<288, 512, SMEM2>>>(x, c1w, c1b, c2b, f1w, f1b, f2w, f2b,
                                     thr, out, t);
    }
    k_tail<<<NB, 256>>>(f1w, f1b, f2w, f2b, thr, out);
}